// round 2
// baseline (speedup 1.0000x reference)
#include <cuda_runtime.h>

// SeathruNeRF RGB renderer, fused single-pass, smem-staged vec3 loads.
// One warp per ray (R=16384), S=256 samples, lane l handles samples c*32+l.
// RGB arrays staged per-chunk into per-warp smem via dense float4 LDG
// (3 lines / 3 wavefronts per array-chunk) instead of stride-12B LDG.32
// (3 wavefronts PER INSTRUCTION). smem reads are stride-3-word -> conflict-free.

#define FULL 0xffffffffu
#define S_SAMPLES 256

__device__ __forceinline__ float clip01(float x) {
    return fminf(fmaxf(x, 0.0f), 1.0f);
}

__global__ __launch_bounds__(256)
void seathru_kernel(const float* __restrict__ orgb,
                    const float* __restrict__ mrgb,
                    const float* __restrict__ dc,
                    const float* __restrict__ bsc,
                    const float* __restrict__ dens,
                    const float* __restrict__ delt,
                    float* __restrict__ out,
                    int R)
{
    // per-warp staging: 4 arrays x 24 float4 (one 32-sample chunk of vec3 data)
    __shared__ float4 stage[8][96];

    const int gwarp = (blockIdx.x * blockDim.x + threadIdx.x) >> 5;
    if (gwarp >= R) return;
    const int lane = threadIdx.x & 31;
    const int w = (threadIdx.x >> 5);
    const int r = gwarp;

    float* sf = (float*)stage[w];

    const float4* o4 = (const float4*)orgb;
    const float4* m4 = (const float4*)mrgb;
    const float4* c4 = (const float4*)dc;
    const float4* b4 = (const float4*)bsc;

    const int base1  = r * S_SAMPLES;   // scalar fields
    const int f4base = r * 192;         // per-array float4 base (768 floats / 4)

    const long long RS = (long long)R * S_SAMPLES;
    float* outT = out + 12LL * R + (long long)r * S_SAMPLES;
    float* outA = outT + RS;
    float* outW = outA + RS;

    float carry0 = 0.f, carry1 = 0.f, carry2 = 0.f, carry3 = 0.f;
    float carry4 = 0.f, carry5 = 0.f, carry6 = 0.f;

    float a_rx = 0.f, a_ry = 0.f, a_rz = 0.f;
    float a_dx = 0.f, a_dy = 0.f, a_dz = 0.f;
    float a_bx = 0.f, a_by = 0.f, a_bz = 0.f;
    float a_m  = 0.f;

    float dc0x = 0.f, dc0y = 0.f, dc0z = 0.f;
    float bs0x = 0.f, bs0y = 0.f, bs0z = 0.f;

    #pragma unroll
    for (int c = 0; c < S_SAMPLES / 32; c++) {
        const int s  = c * 32 + lane;
        const int cb = f4base + c * 24;

        // guard: all lanes done reading previous chunk's staged data
        __syncwarp();
        if (lane < 24) {
            stage[w][lane]      = o4[cb + lane];
            stage[w][24 + lane] = m4[cb + lane];
            stage[w][48 + lane] = c4[cb + lane];
            stage[w][72 + lane] = b4[cb + lane];
        }
        // scalar loads overlap the staging latency
        const float d   = delt[base1 + s];
        const float rho = dens[base1 + s];
        __syncwarp();

        const int l3 = 3 * lane;
        const float ox  = sf[       l3 + 0];
        const float oy  = sf[       l3 + 1];
        const float oz  = sf[       l3 + 2];
        const float mx  = sf[ 96  + l3 + 0];
        const float my  = sf[ 96  + l3 + 1];
        const float mz  = sf[ 96  + l3 + 2];
        const float dcx = sf[192  + l3 + 0];
        const float dcy = sf[192  + l3 + 1];
        const float dcz = sf[192  + l3 + 2];
        const float bx  = sf[288  + l3 + 0];
        const float by  = sf[288  + l3 + 1];
        const float bz  = sf[288  + l3 + 2];

        if (c == 0 && lane == 0) {
            dc0x = dcx; dc0y = dcy; dc0z = dcz;
            bs0x = bx;  bs0y = by;  bs0z = bz;
        }

        const float dd  = d * rho;
        const float bdx = bx * d, bdy = by * d, bdz = bz * d;

        float f0 = dd;
        float f1 = dd + dcx * d;
        float f2 = dd + dcy * d;
        float f3 = dd + dcz * d;
        float f4 = dd + bdx;
        float f5 = dd + bdy;
        float f6 = dd + bdz;

        // inclusive Kogge-Stone warp scan, 7 fields interleaved for ILP
        float i0 = f0, i1 = f1, i2 = f2, i3 = f3, i4 = f4, i5 = f5, i6 = f6;
        #pragma unroll
        for (int off = 1; off < 32; off <<= 1) {
            float n0 = __shfl_up_sync(FULL, i0, off);
            float n1 = __shfl_up_sync(FULL, i1, off);
            float n2 = __shfl_up_sync(FULL, i2, off);
            float n3 = __shfl_up_sync(FULL, i3, off);
            float n4 = __shfl_up_sync(FULL, i4, off);
            float n5 = __shfl_up_sync(FULL, i5, off);
            float n6 = __shfl_up_sync(FULL, i6, off);
            if (lane >= off) {
                i0 += n0; i1 += n1; i2 += n2; i3 += n3;
                i4 += n4; i5 += n5; i6 += n6;
            }
        }

        // exclusive prefix with running carry
        const float e0 = carry0 + i0 - f0;
        const float e1 = carry1 + i1 - f1;
        const float e2 = carry2 + i2 - f2;
        const float e3 = carry3 + i3 - f3;
        const float e4 = carry4 + i4 - f4;
        const float e5 = carry5 + i5 - f5;
        const float e6 = carry6 + i6 - f6;

        carry0 += __shfl_sync(FULL, i0, 31);
        carry1 += __shfl_sync(FULL, i1, 31);
        carry2 += __shfl_sync(FULL, i2, 31);
        carry3 += __shfl_sync(FULL, i3, 31);
        carry4 += __shfl_sync(FULL, i4, 31);
        carry5 += __shfl_sync(FULL, i5, 31);
        carry6 += __shfl_sync(FULL, i6, 31);

        const float T     = __expf(-e0);
        const float alpha = 1.0f - __expf(-dd);
        const float wgt   = T * alpha;

        outT[s] = T;
        outA[s] = alpha;
        outW[s] = wgt;

        a_m  += wgt;
        a_rx += wgt * ox;
        a_ry += wgt * oy;
        a_rz += wgt * oz;

        a_dx += __expf(-e1) * alpha * ox;
        a_dy += __expf(-e2) * alpha * oy;
        a_dz += __expf(-e3) * alpha * oz;

        a_bx += __expf(-e4) * (1.0f - __expf(-bdx)) * mx;
        a_by += __expf(-e5) * (1.0f - __expf(-bdy)) * my;
        a_bz += __expf(-e6) * (1.0f - __expf(-bdz)) * mz;
    }

    // warp butterfly reduce of the 10 accumulators
    #pragma unroll
    for (int off = 16; off >= 1; off >>= 1) {
        a_rx += __shfl_xor_sync(FULL, a_rx, off);
        a_ry += __shfl_xor_sync(FULL, a_ry, off);
        a_rz += __shfl_xor_sync(FULL, a_rz, off);
        a_dx += __shfl_xor_sync(FULL, a_dx, off);
        a_dy += __shfl_xor_sync(FULL, a_dy, off);
        a_dz += __shfl_xor_sync(FULL, a_dz, off);
        a_bx += __shfl_xor_sync(FULL, a_bx, off);
        a_by += __shfl_xor_sync(FULL, a_by, off);
        a_bz += __shfl_xor_sync(FULL, a_bz, off);
        a_m  += __shfl_xor_sync(FULL, a_m,  off);
    }

    if (lane == 0) {
        float* o_rgb  = out + 0LL;
        float* o_rest = out + 3LL * R;
        float* o_dir  = out + 6LL * R;
        float* o_bs   = out + 9LL * R;
        float* o_dc0  = out + 12LL * R + 3LL * RS;
        float* o_bs0  = out + 15LL * R + 3LL * RS;
        float* o_mask = out + 18LL * R + 3LL * RS;

        o_rgb[3 * r + 0] = clip01(a_dx + a_bx);
        o_rgb[3 * r + 1] = clip01(a_dy + a_by);
        o_rgb[3 * r + 2] = clip01(a_dz + a_bz);

        o_rest[3 * r + 0] = clip01(a_rx);
        o_rest[3 * r + 1] = clip01(a_ry);
        o_rest[3 * r + 2] = clip01(a_rz);

        o_dir[3 * r + 0] = clip01(a_dx);
        o_dir[3 * r + 1] = clip01(a_dy);
        o_dir[3 * r + 2] = clip01(a_dz);

        o_bs[3 * r + 0] = clip01(a_bx);
        o_bs[3 * r + 1] = clip01(a_by);
        o_bs[3 * r + 2] = clip01(a_bz);

        o_dc0[3 * r + 0] = dc0x;
        o_dc0[3 * r + 1] = dc0y;
        o_dc0[3 * r + 2] = dc0z;

        o_bs0[3 * r + 0] = bs0x;
        o_bs0[3 * r + 1] = bs0y;
        o_bs0[3 * r + 2] = bs0z;

        o_mask[r] = clip01(a_m);
    }
}

extern "C" void kernel_launch(void* const* d_in, const int* in_sizes, int n_in,
                              void* d_out, int out_size) {
    const float* orgb = (const float*)d_in[0];
    const float* mrgb = (const float*)d_in[1];
    const float* dc   = (const float*)d_in[2];
    const float* bsc  = (const float*)d_in[3];
    const float* dens = (const float*)d_in[4];
    const float* delt = (const float*)d_in[5];
    float* out = (float*)d_out;

    const int R = in_sizes[4] / S_SAMPLES;   // densities is R*S elements

    const int threads = 256;               // 8 warps = 8 rays per block
    const int blocks = (R * 32 + threads - 1) / threads;
    seathru_kernel<<<blocks, threads>>>(orgb, mrgb, dc, bsc, dens, delt, out, R);
}

// round 3
// speedup vs baseline: 1.1359x; 1.1359x over previous
#include <cuda_runtime.h>

// SeathruNeRF RGB renderer, fused single-pass.
// One warp per ray (R=16384), S=256 samples, lane l handles samples c*32+l.
// 7 scan fields: dd, dd+dc_c*delta (x3), dd+bs_c*delta (x3).
// Occupancy-tuned: launch_bounds(256,5) -> <=51 regs -> 40 warps/SM.
// orgb/mrgb loaded AFTER the scan (consumed only post-scan) to shorten
// live ranges; dc0/bs0 outputs written immediately in chunk 0.

#define FULL 0xffffffffu
#define S_SAMPLES 256

__device__ __forceinline__ float clip01(float x) {
    return fminf(fmaxf(x, 0.0f), 1.0f);
}

__global__ __launch_bounds__(256, 5)
void seathru_kernel(const float* __restrict__ orgb,
                    const float* __restrict__ mrgb,
                    const float* __restrict__ dc,
                    const float* __restrict__ bsc,
                    const float* __restrict__ dens,
                    const float* __restrict__ delt,
                    float* __restrict__ out,
                    int R)
{
    const int gwarp = (blockIdx.x * blockDim.x + threadIdx.x) >> 5;
    if (gwarp >= R) return;
    const int lane = threadIdx.x & 31;
    const int r = gwarp;

    const int base1 = r * S_SAMPLES;        // scalar fields
    const int base3 = r * S_SAMPLES * 3;    // rgb fields

    const long long RS = (long long)R * S_SAMPLES;
    float* outT = out + 12LL * R + (long long)r * S_SAMPLES;
    float* outA = outT + RS;
    float* outW = outA + RS;

    float carry0 = 0.f, carry1 = 0.f, carry2 = 0.f, carry3 = 0.f;
    float carry4 = 0.f, carry5 = 0.f, carry6 = 0.f;

    float a_rx = 0.f, a_ry = 0.f, a_rz = 0.f;
    float a_dx = 0.f, a_dy = 0.f, a_dz = 0.f;
    float a_bx = 0.f, a_by = 0.f, a_bz = 0.f;
    float a_m  = 0.f;

    #pragma unroll
    for (int c = 0; c < S_SAMPLES / 32; c++) {
        const int s = c * 32 + lane;

        const float d   = delt[base1 + s];
        const float rho = dens[base1 + s];

        const float dcx = dc[base3 + 3 * s + 0];
        const float dcy = dc[base3 + 3 * s + 1];
        const float dcz = dc[base3 + 3 * s + 2];
        const float bx  = bsc[base3 + 3 * s + 0];
        const float by  = bsc[base3 + 3 * s + 1];
        const float bz  = bsc[base3 + 3 * s + 2];

        // emit the sample-0 coefficient outputs immediately (no persistent regs)
        if (c == 0 && lane == 0) {
            float* o_dc0 = out + 12LL * R + 3LL * RS;
            float* o_bs0 = out + 15LL * R + 3LL * RS;
            o_dc0[3 * r + 0] = dcx;
            o_dc0[3 * r + 1] = dcy;
            o_dc0[3 * r + 2] = dcz;
            o_bs0[3 * r + 0] = bx;
            o_bs0[3 * r + 1] = by;
            o_bs0[3 * r + 2] = bz;
        }

        const float dd  = d * rho;
        const float bdx = bx * d, bdy = by * d, bdz = bz * d;

        float f0 = dd;
        float f1 = dd + dcx * d;
        float f2 = dd + dcy * d;
        float f3 = dd + dcz * d;
        float f4 = dd + bdx;
        float f5 = dd + bdy;
        float f6 = dd + bdz;

        // inclusive Kogge-Stone warp scan, 7 fields interleaved for ILP
        float i0 = f0, i1 = f1, i2 = f2, i3 = f3, i4 = f4, i5 = f5, i6 = f6;
        #pragma unroll
        for (int off = 1; off < 32; off <<= 1) {
            float n0 = __shfl_up_sync(FULL, i0, off);
            float n1 = __shfl_up_sync(FULL, i1, off);
            float n2 = __shfl_up_sync(FULL, i2, off);
            float n3 = __shfl_up_sync(FULL, i3, off);
            float n4 = __shfl_up_sync(FULL, i4, off);
            float n5 = __shfl_up_sync(FULL, i5, off);
            float n6 = __shfl_up_sync(FULL, i6, off);
            if (lane >= off) {
                i0 += n0; i1 += n1; i2 += n2; i3 += n3;
                i4 += n4; i5 += n5; i6 += n6;
            }
        }

        // exclusive prefix with running carry
        const float e0 = carry0 + i0 - f0;
        const float e1 = carry1 + i1 - f1;
        const float e2 = carry2 + i2 - f2;
        const float e3 = carry3 + i3 - f3;
        const float e4 = carry4 + i4 - f4;
        const float e5 = carry5 + i5 - f5;
        const float e6 = carry6 + i6 - f6;

        carry0 += __shfl_sync(FULL, i0, 31);
        carry1 += __shfl_sync(FULL, i1, 31);
        carry2 += __shfl_sync(FULL, i2, 31);
        carry3 += __shfl_sync(FULL, i3, 31);
        carry4 += __shfl_sync(FULL, i4, 31);
        carry5 += __shfl_sync(FULL, i5, 31);
        carry6 += __shfl_sync(FULL, i6, 31);

        // rgb payload loads issued post-scan: consumed only here, keeps
        // register live ranges short so the 5-block residency is spill-free
        const float ox = orgb[base3 + 3 * s + 0];
        const float oy = orgb[base3 + 3 * s + 1];
        const float oz = orgb[base3 + 3 * s + 2];
        const float mx = mrgb[base3 + 3 * s + 0];
        const float my = mrgb[base3 + 3 * s + 1];
        const float mz = mrgb[base3 + 3 * s + 2];

        const float T     = __expf(-e0);
        const float alpha = 1.0f - __expf(-dd);
        const float wgt   = T * alpha;

        outT[s] = T;
        outA[s] = alpha;
        outW[s] = wgt;

        a_m  += wgt;
        a_rx += wgt * ox;
        a_ry += wgt * oy;
        a_rz += wgt * oz;

        a_dx += __expf(-e1) * alpha * ox;
        a_dy += __expf(-e2) * alpha * oy;
        a_dz += __expf(-e3) * alpha * oz;

        a_bx += __expf(-e4) * (1.0f - __expf(-bdx)) * mx;
        a_by += __expf(-e5) * (1.0f - __expf(-bdy)) * my;
        a_bz += __expf(-e6) * (1.0f - __expf(-bdz)) * mz;
    }

    // warp butterfly reduce of the 10 accumulators
    #pragma unroll
    for (int off = 16; off >= 1; off >>= 1) {
        a_rx += __shfl_xor_sync(FULL, a_rx, off);
        a_ry += __shfl_xor_sync(FULL, a_ry, off);
        a_rz += __shfl_xor_sync(FULL, a_rz, off);
        a_dx += __shfl_xor_sync(FULL, a_dx, off);
        a_dy += __shfl_xor_sync(FULL, a_dy, off);
        a_dz += __shfl_xor_sync(FULL, a_dz, off);
        a_bx += __shfl_xor_sync(FULL, a_bx, off);
        a_by += __shfl_xor_sync(FULL, a_by, off);
        a_bz += __shfl_xor_sync(FULL, a_bz, off);
        a_m  += __shfl_xor_sync(FULL, a_m,  off);
    }

    if (lane == 0) {
        float* o_rgb  = out + 0LL;
        float* o_rest = out + 3LL * R;
        float* o_dir  = out + 6LL * R;
        float* o_bs   = out + 9LL * R;
        float* o_mask = out + 18LL * R + 3LL * RS;

        o_rgb[3 * r + 0] = clip01(a_dx + a_bx);
        o_rgb[3 * r + 1] = clip01(a_dy + a_by);
        o_rgb[3 * r + 2] = clip01(a_dz + a_bz);

        o_rest[3 * r + 0] = clip01(a_rx);
        o_rest[3 * r + 1] = clip01(a_ry);
        o_rest[3 * r + 2] = clip01(a_rz);

        o_dir[3 * r + 0] = clip01(a_dx);
        o_dir[3 * r + 1] = clip01(a_dy);
        o_dir[3 * r + 2] = clip01(a_dz);

        o_bs[3 * r + 0] = clip01(a_bx);
        o_bs[3 * r + 1] = clip01(a_by);
        o_bs[3 * r + 2] = clip01(a_bz);

        o_mask[r] = clip01(a_m);
    }
}

extern "C" void kernel_launch(void* const* d_in, const int* in_sizes, int n_in,
                              void* d_out, int out_size) {
    const float* orgb = (const float*)d_in[0];
    const float* mrgb = (const float*)d_in[1];
    const float* dc   = (const float*)d_in[2];
    const float* bsc  = (const float*)d_in[3];
    const float* dens = (const float*)d_in[4];
    const float* delt = (const float*)d_in[5];
    float* out = (float*)d_out;

    const int R = in_sizes[4] / S_SAMPLES;   // densities is R*S elements

    const int threads = 256;               // 8 warps = 8 rays per block
    const int blocks = (R * 32 + threads - 1) / threads;
    seathru_kernel<<<blocks, threads>>>(orgb, mrgb, dc, bsc, dens, delt, out, R);
}

// round 4
// speedup vs baseline: 1.2553x; 1.1051x over previous
#include <cuda_runtime.h>

// SeathruNeRF RGB renderer, fused single-pass, software-pipelined loads.
// One warp per ray (R=16384), S=256 samples, lane l handles samples c*32+l.
// Next chunk's scan inputs are prefetched during the current chunk's
// shuffle-scan; orgb/mrgb issued pre-scan so their latency hides under it.

#define FULL 0xffffffffu
#define S_SAMPLES 256

__device__ __forceinline__ float clip01(float x) {
    return fminf(fmaxf(x, 0.0f), 1.0f);
}

struct ScanIn {
    float d, rho, dcx, dcy, dcz, bx, by, bz;
};

__device__ __forceinline__ ScanIn load_scan_in(const float* __restrict__ dc,
                                               const float* __restrict__ bsc,
                                               const float* __restrict__ dens,
                                               const float* __restrict__ delt,
                                               int base1, int base3, int s)
{
    ScanIn v;
    v.d   = __ldcs(&delt[base1 + s]);
    v.rho = __ldcs(&dens[base1 + s]);
    v.dcx = __ldcs(&dc[base3 + 3 * s + 0]);
    v.dcy = __ldcs(&dc[base3 + 3 * s + 1]);
    v.dcz = __ldcs(&dc[base3 + 3 * s + 2]);
    v.bx  = __ldcs(&bsc[base3 + 3 * s + 0]);
    v.by  = __ldcs(&bsc[base3 + 3 * s + 1]);
    v.bz  = __ldcs(&bsc[base3 + 3 * s + 2]);
    return v;
}

__global__ __launch_bounds__(256, 4)
void seathru_kernel(const float* __restrict__ orgb,
                    const float* __restrict__ mrgb,
                    const float* __restrict__ dc,
                    const float* __restrict__ bsc,
                    const float* __restrict__ dens,
                    const float* __restrict__ delt,
                    float* __restrict__ out,
                    int R)
{
    const int gwarp = (blockIdx.x * blockDim.x + threadIdx.x) >> 5;
    if (gwarp >= R) return;
    const int lane = threadIdx.x & 31;
    const int r = gwarp;

    const int base1 = r * S_SAMPLES;        // scalar fields
    const int base3 = r * S_SAMPLES * 3;    // rgb fields

    const long long RS = (long long)R * S_SAMPLES;
    float* outT = out + 12LL * R + (long long)r * S_SAMPLES;
    float* outA = outT + RS;
    float* outW = outA + RS;

    float carry0 = 0.f, carry1 = 0.f, carry2 = 0.f, carry3 = 0.f;
    float carry4 = 0.f, carry5 = 0.f, carry6 = 0.f;

    float a_rx = 0.f, a_ry = 0.f, a_rz = 0.f;
    float a_dx = 0.f, a_dy = 0.f, a_dz = 0.f;
    float a_bx = 0.f, a_by = 0.f, a_bz = 0.f;
    float a_m  = 0.f;

    // prologue: chunk 0 inputs
    ScanIn cur = load_scan_in(dc, bsc, dens, delt, base1, base3, lane);

    #pragma unroll
    for (int c = 0; c < S_SAMPLES / 32; c++) {
        const int s = c * 32 + lane;

        // prefetch next chunk's scan inputs: in flight during this scan
        ScanIn nxt = cur;
        if (c < S_SAMPLES / 32 - 1) {
            nxt = load_scan_in(dc, bsc, dens, delt, base1, base3, s + 32);
        }

        // rgb payload loads issued pre-scan: latency hidden under the scan
        const float ox = __ldcs(&orgb[base3 + 3 * s + 0]);
        const float oy = __ldcs(&orgb[base3 + 3 * s + 1]);
        const float oz = __ldcs(&orgb[base3 + 3 * s + 2]);
        const float mx = __ldcs(&mrgb[base3 + 3 * s + 0]);
        const float my = __ldcs(&mrgb[base3 + 3 * s + 1]);
        const float mz = __ldcs(&mrgb[base3 + 3 * s + 2]);

        // emit the sample-0 coefficient outputs immediately
        if (c == 0 && lane == 0) {
            float* o_dc0 = out + 12LL * R + 3LL * RS;
            float* o_bs0 = out + 15LL * R + 3LL * RS;
            o_dc0[3 * r + 0] = cur.dcx;
            o_dc0[3 * r + 1] = cur.dcy;
            o_dc0[3 * r + 2] = cur.dcz;
            o_bs0[3 * r + 0] = cur.bx;
            o_bs0[3 * r + 1] = cur.by;
            o_bs0[3 * r + 2] = cur.bz;
        }

        const float dd  = cur.d * cur.rho;
        const float bdx = cur.bx * cur.d;
        const float bdy = cur.by * cur.d;
        const float bdz = cur.bz * cur.d;

        const float f0 = dd;
        const float f1 = dd + cur.dcx * cur.d;
        const float f2 = dd + cur.dcy * cur.d;
        const float f3 = dd + cur.dcz * cur.d;
        const float f4 = dd + bdx;
        const float f5 = dd + bdy;
        const float f6 = dd + bdz;

        // inclusive Kogge-Stone warp scan, 7 fields interleaved for ILP
        float i0 = f0, i1 = f1, i2 = f2, i3 = f3, i4 = f4, i5 = f5, i6 = f6;
        #pragma unroll
        for (int off = 1; off < 32; off <<= 1) {
            float n0 = __shfl_up_sync(FULL, i0, off);
            float n1 = __shfl_up_sync(FULL, i1, off);
            float n2 = __shfl_up_sync(FULL, i2, off);
            float n3 = __shfl_up_sync(FULL, i3, off);
            float n4 = __shfl_up_sync(FULL, i4, off);
            float n5 = __shfl_up_sync(FULL, i5, off);
            float n6 = __shfl_up_sync(FULL, i6, off);
            if (lane >= off) {
                i0 += n0; i1 += n1; i2 += n2; i3 += n3;
                i4 += n4; i5 += n5; i6 += n6;
            }
        }

        // exclusive prefix with running carry
        const float e0 = carry0 + i0 - f0;
        const float e1 = carry1 + i1 - f1;
        const float e2 = carry2 + i2 - f2;
        const float e3 = carry3 + i3 - f3;
        const float e4 = carry4 + i4 - f4;
        const float e5 = carry5 + i5 - f5;
        const float e6 = carry6 + i6 - f6;

        carry0 += __shfl_sync(FULL, i0, 31);
        carry1 += __shfl_sync(FULL, i1, 31);
        carry2 += __shfl_sync(FULL, i2, 31);
        carry3 += __shfl_sync(FULL, i3, 31);
        carry4 += __shfl_sync(FULL, i4, 31);
        carry5 += __shfl_sync(FULL, i5, 31);
        carry6 += __shfl_sync(FULL, i6, 31);

        const float T     = __expf(-e0);
        const float alpha = 1.0f - __expf(-dd);
        const float wgt   = T * alpha;

        __stcs(&outT[s], T);
        __stcs(&outA[s], alpha);
        __stcs(&outW[s], wgt);

        a_m  += wgt;
        a_rx += wgt * ox;
        a_ry += wgt * oy;
        a_rz += wgt * oz;

        a_dx += __expf(-e1) * alpha * ox;
        a_dy += __expf(-e2) * alpha * oy;
        a_dz += __expf(-e3) * alpha * oz;

        a_bx += __expf(-e4) * (1.0f - __expf(-bdx)) * mx;
        a_by += __expf(-e5) * (1.0f - __expf(-bdy)) * my;
        a_bz += __expf(-e6) * (1.0f - __expf(-bdz)) * mz;

        cur = nxt;
    }

    // warp butterfly reduce of the 10 accumulators
    #pragma unroll
    for (int off = 16; off >= 1; off >>= 1) {
        a_rx += __shfl_xor_sync(FULL, a_rx, off);
        a_ry += __shfl_xor_sync(FULL, a_ry, off);
        a_rz += __shfl_xor_sync(FULL, a_rz, off);
        a_dx += __shfl_xor_sync(FULL, a_dx, off);
        a_dy += __shfl_xor_sync(FULL, a_dy, off);
        a_dz += __shfl_xor_sync(FULL, a_dz, off);
        a_bx += __shfl_xor_sync(FULL, a_bx, off);
        a_by += __shfl_xor_sync(FULL, a_by, off);
        a_bz += __shfl_xor_sync(FULL, a_bz, off);
        a_m  += __shfl_xor_sync(FULL, a_m,  off);
    }

    if (lane == 0) {
        float* o_rgb  = out + 0LL;
        float* o_rest = out + 3LL * R;
        float* o_dir  = out + 6LL * R;
        float* o_bs   = out + 9LL * R;
        float* o_mask = out + 18LL * R + 3LL * RS;

        o_rgb[3 * r + 0] = clip01(a_dx + a_bx);
        o_rgb[3 * r + 1] = clip01(a_dy + a_by);
        o_rgb[3 * r + 2] = clip01(a_dz + a_bz);

        o_rest[3 * r + 0] = clip01(a_rx);
        o_rest[3 * r + 1] = clip01(a_ry);
        o_rest[3 * r + 2] = clip01(a_rz);

        o_dir[3 * r + 0] = clip01(a_dx);
        o_dir[3 * r + 1] = clip01(a_dy);
        o_dir[3 * r + 2] = clip01(a_dz);

        o_bs[3 * r + 0] = clip01(a_bx);
        o_bs[3 * r + 1] = clip01(a_by);
        o_bs[3 * r + 2] = clip01(a_bz);

        o_mask[r] = clip01(a_m);
    }
}

extern "C" void kernel_launch(void* const* d_in, const int* in_sizes, int n_in,
                              void* d_out, int out_size) {
    const float* orgb = (const float*)d_in[0];
    const float* mrgb = (const float*)d_in[1];
    const float* dc   = (const float*)d_in[2];
    const float* bsc  = (const float*)d_in[3];
    const float* dens = (const float*)d_in[4];
    const float* delt = (const float*)d_in[5];
    float* out = (float*)d_out;

    const int R = in_sizes[4] / S_SAMPLES;   // densities is R*S elements

    const int threads = 256;               // 8 warps = 8 rays per block
    const int blocks = (R * 32 + threads - 1) / threads;
    seathru_kernel<<<blocks, threads>>>(orgb, mrgb, dc, bsc, dens, delt, out, R);
}

// round 5
// speedup vs baseline: 1.4172x; 1.1289x over previous
#include <cuda_runtime.h>

// SeathruNeRF RGB renderer: fused, software-pipelined, 2 samples per lane.
// One warp per ray (R=16384), S=256 = 4 chunks of 64; lane l owns samples
// c*64+2l and c*64+2l+1. Pair-sum + 5-step warp scan halves SHFL count;
// float2 LDG/STG halves memory instruction count at equal bytes.

#define FULL 0xffffffffu
#define S_SAMPLES 256
#define NCHUNK 4

__device__ __forceinline__ float clip01(float x) {
    return fminf(fmaxf(x, 0.0f), 1.0f);
}

// scan-critical inputs for one lane's 2 samples
struct ScanIn {
    float d0, d1, rho0, rho1;
    float dc0[3], dc1[3];
    float bs0[3], bs1[3];
};

__device__ __forceinline__ ScanIn load_scan_in(const float* __restrict__ dc,
                                               const float* __restrict__ bsc,
                                               const float* __restrict__ dens,
                                               const float* __restrict__ delt,
                                               int base1, int base3,
                                               int chunk, int lane)
{
    ScanIn v;
    const float2* dl2 = (const float2*)(delt + base1 + chunk * 64);
    const float2* dn2 = (const float2*)(dens + base1 + chunk * 64);
    float2 dp = __ldcs(&dl2[lane]);
    float2 rp = __ldcs(&dn2[lane]);
    v.d0 = dp.x; v.d1 = dp.y; v.rho0 = rp.x; v.rho1 = rp.y;

    const float2* c2 = (const float2*)(dc  + base3 + chunk * 192);
    const float2* b2 = (const float2*)(bsc + base3 + chunk * 192);
    float2 A = __ldcs(&c2[3 * lane + 0]);
    float2 B = __ldcs(&c2[3 * lane + 1]);
    float2 C = __ldcs(&c2[3 * lane + 2]);
    v.dc0[0] = A.x; v.dc0[1] = A.y; v.dc0[2] = B.x;
    v.dc1[0] = B.y; v.dc1[1] = C.x; v.dc1[2] = C.y;
    A = __ldcs(&b2[3 * lane + 0]);
    B = __ldcs(&b2[3 * lane + 1]);
    C = __ldcs(&b2[3 * lane + 2]);
    v.bs0[0] = A.x; v.bs0[1] = A.y; v.bs0[2] = B.x;
    v.bs1[0] = B.y; v.bs1[1] = C.x; v.bs1[2] = C.y;
    return v;
}

__global__ __launch_bounds__(256, 3)
void seathru_kernel(const float* __restrict__ orgb,
                    const float* __restrict__ mrgb,
                    const float* __restrict__ dc,
                    const float* __restrict__ bsc,
                    const float* __restrict__ dens,
                    const float* __restrict__ delt,
                    float* __restrict__ out,
                    int R)
{
    const int gwarp = (blockIdx.x * blockDim.x + threadIdx.x) >> 5;
    if (gwarp >= R) return;
    const int lane = threadIdx.x & 31;
    const int r = gwarp;

    const int base1 = r * S_SAMPLES;
    const int base3 = r * S_SAMPLES * 3;

    const long long RS = (long long)R * S_SAMPLES;
    float* outT = out + 12LL * R + (long long)r * S_SAMPLES;
    float* outA = outT + RS;
    float* outW = outA + RS;

    float carry[7];
    #pragma unroll
    for (int k = 0; k < 7; k++) carry[k] = 0.f;

    float a_rx = 0.f, a_ry = 0.f, a_rz = 0.f;
    float a_dx = 0.f, a_dy = 0.f, a_dz = 0.f;
    float a_bx = 0.f, a_by = 0.f, a_bz = 0.f;
    float a_m  = 0.f;

    ScanIn cur = load_scan_in(dc, bsc, dens, delt, base1, base3, 0, lane);

    #pragma unroll
    for (int c = 0; c < NCHUNK; c++) {
        // prefetch next chunk's scan inputs (in flight during this scan)
        ScanIn nxt = cur;
        if (c < NCHUNK - 1) {
            nxt = load_scan_in(dc, bsc, dens, delt, base1, base3, c + 1, lane);
        }

        // rgb payloads, issued pre-scan (float2 vector loads)
        const float2* o2 = (const float2*)(orgb + base3 + c * 192);
        const float2* m2 = (const float2*)(mrgb + base3 + c * 192);
        float2 oA = __ldcs(&o2[3 * lane + 0]);
        float2 oB = __ldcs(&o2[3 * lane + 1]);
        float2 oC = __ldcs(&o2[3 * lane + 2]);
        float2 mA = __ldcs(&m2[3 * lane + 0]);
        float2 mB = __ldcs(&m2[3 * lane + 1]);
        float2 mC = __ldcs(&m2[3 * lane + 2]);

        if (c == 0 && lane == 0) {
            float* o_dc0 = out + 12LL * R + 3LL * RS;
            float* o_bs0 = out + 15LL * R + 3LL * RS;
            o_dc0[3 * r + 0] = cur.dc0[0];
            o_dc0[3 * r + 1] = cur.dc0[1];
            o_dc0[3 * r + 2] = cur.dc0[2];
            o_bs0[3 * r + 0] = cur.bs0[0];
            o_bs0[3 * r + 1] = cur.bs0[1];
            o_bs0[3 * r + 2] = cur.bs0[2];
        }

        const float dd0 = cur.d0 * cur.rho0;
        const float dd1 = cur.d1 * cur.rho1;

        float bd0[3], bd1[3];
        #pragma unroll
        for (int k = 0; k < 3; k++) {
            bd0[k] = cur.bs0[k] * cur.d0;
            bd1[k] = cur.bs1[k] * cur.d1;
        }

        // field values at sample0, and pair sums (sample0+sample1)
        float fs0[7], p[7];
        fs0[0] = dd0;
        p[0]   = dd0 + dd1;
        #pragma unroll
        for (int k = 0; k < 3; k++) {
            fs0[1 + k] = dd0 + cur.dc0[k] * cur.d0;
            p[1 + k]   = fs0[1 + k] + dd1 + cur.dc1[k] * cur.d1;
            fs0[4 + k] = dd0 + bd0[k];
            p[4 + k]   = fs0[4 + k] + dd1 + bd1[k];
        }

        // inclusive Kogge-Stone scan of the 7 pair-sum fields
        float inc[7];
        #pragma unroll
        for (int k = 0; k < 7; k++) inc[k] = p[k];
        #pragma unroll
        for (int off = 1; off < 32; off <<= 1) {
            float n[7];
            #pragma unroll
            for (int k = 0; k < 7; k++) n[k] = __shfl_up_sync(FULL, inc[k], off);
            if (lane >= off) {
                #pragma unroll
                for (int k = 0; k < 7; k++) inc[k] += n[k];
            }
        }

        // exclusive prefixes per sample
        float e0[7], e1[7];
        #pragma unroll
        for (int k = 0; k < 7; k++) {
            e0[k] = carry[k] + inc[k] - p[k];
            e1[k] = e0[k] + fs0[k];
            carry[k] += __shfl_sync(FULL, inc[k], 31);
        }

        const float T0     = __expf(-e0[0]);
        const float T1     = __expf(-e1[0]);
        const float alpha0 = 1.0f - __expf(-dd0);
        const float alpha1 = 1.0f - __expf(-dd1);
        const float w0     = T0 * alpha0;
        const float w1     = T1 * alpha1;

        {
            float2* t2 = (float2*)(outT + c * 64);
            float2* a2 = (float2*)(outA + c * 64);
            float2* w2 = (float2*)(outW + c * 64);
            __stcs(&t2[lane], make_float2(T0, T1));
            __stcs(&a2[lane], make_float2(alpha0, alpha1));
            __stcs(&w2[lane], make_float2(w0, w1));
        }

        // reassemble vec3 components per sample from the float2 slices
        const float ox0 = oA.x, oy0 = oA.y, oz0 = oB.x;
        const float ox1 = oB.y, oy1 = oC.x, oz1 = oC.y;
        const float mx0 = mA.x, my0 = mA.y, mz0 = mB.x;
        const float mx1 = mB.y, my1 = mC.x, mz1 = mC.y;

        a_m  += w0 + w1;
        a_rx += w0 * ox0 + w1 * ox1;
        a_ry += w0 * oy0 + w1 * oy1;
        a_rz += w0 * oz0 + w1 * oz1;

        a_dx += __expf(-e0[1]) * alpha0 * ox0 + __expf(-e1[1]) * alpha1 * ox1;
        a_dy += __expf(-e0[2]) * alpha0 * oy0 + __expf(-e1[2]) * alpha1 * oy1;
        a_dz += __expf(-e0[3]) * alpha0 * oz0 + __expf(-e1[3]) * alpha1 * oz1;

        a_bx += __expf(-e0[4]) * (1.0f - __expf(-bd0[0])) * mx0
              + __expf(-e1[4]) * (1.0f - __expf(-bd1[0])) * mx1;
        a_by += __expf(-e0[5]) * (1.0f - __expf(-bd0[1])) * my0
              + __expf(-e1[5]) * (1.0f - __expf(-bd1[1])) * my1;
        a_bz += __expf(-e0[6]) * (1.0f - __expf(-bd0[2])) * mz0
              + __expf(-e1[6]) * (1.0f - __expf(-bd1[2])) * mz1;

        cur = nxt;
    }

    // warp butterfly reduce of the 10 accumulators
    #pragma unroll
    for (int off = 16; off >= 1; off >>= 1) {
        a_rx += __shfl_xor_sync(FULL, a_rx, off);
        a_ry += __shfl_xor_sync(FULL, a_ry, off);
        a_rz += __shfl_xor_sync(FULL, a_rz, off);
        a_dx += __shfl_xor_sync(FULL, a_dx, off);
        a_dy += __shfl_xor_sync(FULL, a_dy, off);
        a_dz += __shfl_xor_sync(FULL, a_dz, off);
        a_bx += __shfl_xor_sync(FULL, a_bx, off);
        a_by += __shfl_xor_sync(FULL, a_by, off);
        a_bz += __shfl_xor_sync(FULL, a_bz, off);
        a_m  += __shfl_xor_sync(FULL, a_m,  off);
    }

    if (lane == 0) {
        float* o_rgb  = out + 0LL;
        float* o_rest = out + 3LL * R;
        float* o_dir  = out + 6LL * R;
        float* o_bs   = out + 9LL * R;
        float* o_mask = out + 18LL * R + 3LL * RS;

        o_rgb[3 * r + 0] = clip01(a_dx + a_bx);
        o_rgb[3 * r + 1] = clip01(a_dy + a_by);
        o_rgb[3 * r + 2] = clip01(a_dz + a_bz);

        o_rest[3 * r + 0] = clip01(a_rx);
        o_rest[3 * r + 1] = clip01(a_ry);
        o_rest[3 * r + 2] = clip01(a_rz);

        o_dir[3 * r + 0] = clip01(a_dx);
        o_dir[3 * r + 1] = clip01(a_dy);
        o_dir[3 * r + 2] = clip01(a_dz);

        o_bs[3 * r + 0] = clip01(a_bx);
        o_bs[3 * r + 1] = clip01(a_by);
        o_bs[3 * r + 2] = clip01(a_bz);

        o_mask[r] = clip01(a_m);
    }
}

extern "C" void kernel_launch(void* const* d_in, const int* in_sizes, int n_in,
                              void* d_out, int out_size) {
    const float* orgb = (const float*)d_in[0];
    const float* mrgb = (const float*)d_in[1];
    const float* dc   = (const float*)d_in[2];
    const float* bsc  = (const float*)d_in[3];
    const float* dens = (const float*)d_in[4];
    const float* delt = (const float*)d_in[5];
    float* out = (float*)d_out;

    const int R = in_sizes[4] / S_SAMPLES;   // densities is R*S elements

    const int threads = 256;               // 8 warps = 8 rays per block
    const int blocks = (R * 32 + threads - 1) / threads;
    seathru_kernel<<<blocks, threads>>>(orgb, mrgb, dc, bsc, dens, delt, out, R);
}